// round 2
// baseline (speedup 1.0000x reference)
#include <cuda_runtime.h>
#include <math.h>

#define NRAYS   131072
#define NPTS    64
#define NIMP    64
#define NEARF   0.1f
#define FARF    2.0f
#define STEPF   ((FARF - NEARF) / 63.0f)
#define BLK     128

// scratch (no allocation allowed)
__device__ float    g_rd[NRAYS];
__device__ unsigned g_min_bits;
__device__ unsigned g_max_bits;

__device__ __forceinline__ float sigmoidf(float x) {
    return __fdividef(1.0f, 1.0f + __expf(-x));
}

__device__ __forceinline__ float depth_at(int p) {
    return fmaf((float)p, STEPF, NEARF);
}

__global__ void init_minmax() {
    g_min_bits = 0xFFFFFFFFu;  // > any positive float bit pattern
    g_max_bits = 0u;
}

__global__ __launch_bounds__(BLK) void nerf_main(const float* __restrict__ TM,
                                                 const float* __restrict__ WQ,
                                                 float* __restrict__ out)
{
    __shared__ float s_fd[NIMP * BLK];   // per-thread fine depths, [q*BLK + tid]

    const int tid = threadIdx.x;
    const int r   = blockIdx.x * BLK + tid;
    const int bb_ = r >> 16;            // batch
    const int n   = r & 0xFFFF;         // pixel index within batch
    const int pi  = n >> 8;
    const int pj  = n & 0xFF;

    // camera dir
    const float cx = (1.0f - (float)pj * (2.0f / 255.0f)) * (1.0f / 4.2f);
    const float cy = (1.0f - (float)pi * (2.0f / 255.0f)) * (1.0f / 4.2f);

    const float* M = TM + bb_ * 12;
    const float dx = __ldg(M + 0) * cx + __ldg(M + 1) * cy + __ldg(M + 2);
    const float ox = __ldg(M + 3);
    const float dy = __ldg(M + 4) * cx + __ldg(M + 5) * cy + __ldg(M + 6);
    const float oy = __ldg(M + 7);
    const float dz = __ldg(M + 8) * cx + __ldg(M + 9) * cy + __ldg(M + 10);
    const float oz = __ldg(M + 11);

    // feat_j(d) = a[j] + d * b[j]
    float a[4], bb[4];
#pragma unroll
    for (int c = 0; c < 4; c++) {
        const float w0 = __ldg(WQ + 0 * 4 + c);
        const float w1 = __ldg(WQ + 1 * 4 + c);
        const float w2 = __ldg(WQ + 2 * 4 + c);
        const float w3 = __ldg(WQ + 3 * 4 + c);
        const float w4 = __ldg(WQ + 4 * 4 + c);
        const float w5 = __ldg(WQ + 5 * 4 + c);
        bb[c] = dx * w0 + dy * w1 + dz * w2;
        a[c]  = ox * w0 + oy * w1 + oz * w2 + dx * w3 + dy * w4 + dz * w5;
    }

    // ---------------- Phase A: coarse march ----------------
    float T = 1.0f, cv0 = 0.f, cv1 = 0.f, cv2 = 0.f, wsum = 0.f;
#pragma unroll 8
    for (int p = 0; p < NPTS; p++) {
        const float d  = depth_at(p);
        const float op = sigmoidf(fmaf(d, bb[0], a[0]));
        const float w  = op * T;
        T *= (1.0f - op);
        cv0 = fmaf(w, sigmoidf(fmaf(d, bb[1], a[1])), cv0);
        cv1 = fmaf(w, sigmoidf(fmaf(d, bb[2], a[2])), cv1);
        cv2 = fmaf(w, sigmoidf(fmaf(d, bb[3], a[3])), cv2);
        wsum += w;
    }
    // c_img: out[b*3*65536 + c*65536 + n]
    {
        float* o = out + bb_ * 196608 + n;
        o[0]       = cv0;
        o[65536]   = cv1;
        o[131072]  = cv2;
    }

    // ---------------- Phase B: inverse-CDF sampling (merge scan) ----------------
    {
        const float S = wsum + (float)NPTS * 1e-5f;   // sum(wpad)
        float Tb = 1.0f;
        int   p  = 0;
        // cdf[0]
        float op0      = sigmoidf(fmaf(depth_at(0), bb[0], a[0]));
        float w0       = op0 * Tb;
        Tb *= (1.0f - op0);
        float cdf_prev = 0.0f;
        float cdf_cur  = __fdividef(w0 + 1e-5f, S);
        float bin_prev = 0.0f;

        for (int ii = 0; ii <= NIMP; ii++) {
            const float u = (float)ii * (1.0f / (float)NIMP);
            while (p < NPTS - 1 && cdf_cur <= u) {
                p++;
                const float d  = depth_at(p);
                const float op = sigmoidf(fmaf(d, bb[0], a[0]));
                const float w  = op * Tb;
                Tb *= (1.0f - op);
                cdf_prev = cdf_cur;
                cdf_cur += __fdividef(w + 1e-5f, S);
            }
            float c0, c1, d0, d1;
            if (cdf_cur <= u) {                 // p == 63, idx = 64
                c0 = c1 = cdf_cur; d0 = d1 = depth_at(NPTS - 1);
            } else if (p == 0) {                // idx = 0
                c0 = c1 = cdf_cur; d0 = d1 = depth_at(0);
            } else {                            // 1 <= idx <= 63
                c0 = cdf_prev; c1 = cdf_cur;
                d0 = depth_at(p - 1); d1 = depth_at(p);
            }
            float den = c1 - c0;
            den = (den < 1e-8f) ? 1.0f : den;
            const float tt  = __saturatef(__fdividef(u - c0, den));
            const float bin = fmaf(tt, d1 - d0, d0);
            if (ii > 0)
                s_fd[(ii - 1) * BLK + tid] = 0.5f * (bin_prev + bin);
            bin_prev = bin;
        }
    }

    // ---------------- Phase C: merged fine march (2-way merge, coarse wins ties) ----------------
    float T2 = 1.0f, fv0 = 0.f, fv1 = 0.f, fv2 = 0.f, wsum2 = 0.f, rdacc = 0.f;
    {
        int cp = 0, fq = 0;
#pragma unroll 4
        for (int s = 0; s < NPTS + NIMP; s++) {
            const float dc = (cp < NPTS) ? depth_at(cp) : 1e30f;
            const float df = (fq < NIMP) ? s_fd[fq * BLK + tid] : 1e30f;
            float d;
            if (dc <= df) { d = dc; cp++; }
            else          { d = df; fq++; }
            const float op = sigmoidf(fmaf(d, bb[0], a[0]));
            const float w  = op * T2;
            T2 *= (1.0f - op);
            fv0 = fmaf(w, sigmoidf(fmaf(d, bb[1], a[1])), fv0);
            fv1 = fmaf(w, sigmoidf(fmaf(d, bb[2], a[2])), fv1);
            fv2 = fmaf(w, sigmoidf(fmaf(d, bb[3], a[3])), fv2);
            wsum2 += w;
            rdacc = fmaf(w, d, rdacc);
        }
    }
    // f_img
    {
        float* o = out + 393216 + bb_ * 196608 + n;
        o[0]      = fv0;
        o[65536]  = fv1;
        o[131072] = fv2;
    }

    // ray depth: rd = sum(w*d) + (1 - clip(sum w,0,1)) * max(d_all)  (max == 2.0 globally)
    const float f_op = fminf(fmaxf(wsum2, 0.0f), 1.0f);
    const float rd   = rdacc + (1.0f - f_op) * 2.0f;
    g_rd[r] = rd;

    // block-level min/max -> global atomics (positive floats compare as uints)
    unsigned vmin = __float_as_uint(rd);
    unsigned vmax = vmin;
#pragma unroll
    for (int o = 16; o > 0; o >>= 1) {
        vmin = min(vmin, __shfl_xor_sync(0xFFFFFFFFu, vmin, o));
        vmax = max(vmax, __shfl_xor_sync(0xFFFFFFFFu, vmax, o));
    }
    if ((tid & 31) == 0) {
        atomicMin(&g_min_bits, vmin);
        atomicMax(&g_max_bits, vmax);
    }
}

__global__ __launch_bounds__(256) void norm_depth(float* __restrict__ out)
{
    const int idx = blockIdx.x * 256 + threadIdx.x;
    const float mn = __uint_as_float(g_min_bits);
    const float mx = __uint_as_float(g_max_bits);
    out[786432 + idx] = (g_rd[idx] - mn) / (mx - mn);
}

extern "C" void kernel_launch(void* const* d_in, const int* in_sizes, int n_in,
                              void* d_out, int out_size)
{
    const float* TM = (const float*)d_in[0];   // transform_matrix (2,3,4)
    const float* WQ = (const float*)d_in[1];   // W_query (6,4)
    float* out = (float*)d_out;

    init_minmax<<<1, 1>>>();
    nerf_main<<<NRAYS / BLK, BLK>>>(TM, WQ, out);
    norm_depth<<<NRAYS / 256, 256>>>(out);
}